// round 14
// baseline (speedup 1.0000x reference)
#include <cuda_runtime.h>
#include <cuda_fp16.h>
#include <cstdint>

#define NNODE 32
#define CIN   60
#define HID   128
#define KCH   5

// ---- fragment-order packed constants (all L2-resident, loaded direct) ----
__device__ __align__(16) uint32_t g_W1fh[4][8][4][32][4];  // A-op frag, layer1
__device__ __align__(16) uint32_t g_W2fh[4][8][8][32][4];  // A-op frag, layer2
__device__ __align__(16) uint32_t g_Af[4][2][2][32][4];    // B-op frag, chebyshev
__device__ __align__(16) float    g_FCf[2][4][2][4][32][4];// FC frag order
__device__ float g_B1[128];
__device__ float g_B2[128];

__device__ __forceinline__ uint32_t pack_hh(__half a, __half b) {
    return (uint32_t)__half_as_ushort(a) | ((uint32_t)__half_as_ushort(b) << 16);
}

// ------------------------------------------------------------------
__global__ void precompute_kernel(const float* __restrict__ adj,
                                  const float* __restrict__ adj_bias,
                                  const float* __restrict__ w1,
                                  const float* __restrict__ b1,
                                  const float* __restrict__ w2,
                                  const float* __restrict__ b2,
                                  const float* __restrict__ fc_w) {
    __shared__ float a[NNODE][NNODE];
    __shared__ float L[NNODE][NNODE];
    __shared__ float A3[NNODE][NNODE];
    __shared__ float A4[NNODE][NNODE];
    __shared__ float dre[NNODE];

    int tid = threadIdx.x;
    int n = tid >> 5, m = tid & 31;

    float bias = adj_bias[0];
    a[n][m] = fmaxf(adj[n * NNODE + m] + bias, 0.0f);
    __syncthreads();
    if (m == 0) {
        float s = 0.0f;
        for (int j = 0; j < NNODE; j++) s += a[n][j];
        dre[n] = 1.0f / sqrtf(s + 1e-5f);
    }
    __syncthreads();
    L[n][m] = (n == m ? 1.0f : 0.0f) - dre[n] * a[n][m] * dre[m];
    __syncthreads();
    float s = 0.0f;
    for (int j = 0; j < NNODE; j++) s += L[n][j] * L[j][m];
    A3[n][m] = 2.0f * s - (n == m ? 1.0f : 0.0f);
    __syncthreads();
    float s2 = 0.0f;
    for (int j = 0; j < NNODE; j++) s2 += L[n][j] * A3[j][m];
    A4[n][m] = 2.0f * s2 - L[n][m];
    __syncthreads();

    // Chebyshev B-operand fragments (ldsm.m8n8.x4 emulation)
    for (int idx = tid; idx < 4 * 2 * 2 * 32; idx += blockDim.x) {
        int lane = idx & 31;
        int np = (idx >> 5) & 1;
        int kh = (idx >> 6) & 1;
        int k = idx >> 7;
        for (int q = 0; q < 4; q++) {
            int rn = np * 16 + (q & 1) * 8 + (lane >> 2);
            int cm = kh * 16 + (q >> 1) * 8 + 2 * (lane & 3);
            float v0, v1;
            if (k == 0)      { v0 = (rn == cm) ? 1.0f : 0.0f; v1 = (rn == cm + 1) ? 1.0f : 0.0f; }
            else if (k == 1) { v0 = L[rn][cm];  v1 = L[rn][cm + 1]; }
            else if (k == 2) { v0 = A3[rn][cm]; v1 = A3[rn][cm + 1]; }
            else             { v0 = A4[rn][cm]; v1 = A4[rn][cm + 1]; }
            g_Af[k][kh][np][lane][q] =
                pack_hh(__float2half_rn(v0), __float2half_rn(v1));
        }
    }

    // W1 fragments: row=o, col=c (zero pad c>=60)
    for (int idx = tid; idx < 4 * 8 * 4 * 32; idx += blockDim.x) {
        int lane = idx & 31;
        int ct = (idx >> 5) & 3;
        int ot = (idx >> 7) & 7;
        int k = idx >> 10;
        int r0 = lane >> 2, cp = (lane & 3) * 2;
        for (int ai = 0; ai < 4; ai++) {
            int row = ot * 16 + r0 + (ai & 1) * 8;
            int col = ct * 16 + cp + (ai >> 1) * 8;
            float v0 = (col < CIN) ? w1[(col * KCH + k + 1) * HID + row] : 0.0f;
            float v1 = (col + 1 < CIN) ? w1[((col + 1) * KCH + k + 1) * HID + row] : 0.0f;
            g_W1fh[k][ot][ct][lane][ai] =
                pack_hh(__float2half_rn(v0), __float2half_rn(v1));
        }
    }
    // W2 fragments: row=o2, col=o
    for (int idx = tid; idx < 4 * 8 * 8 * 32; idx += blockDim.x) {
        int lane = idx & 31;
        int ct = (idx >> 5) & 7;
        int ot = (idx >> 8) & 7;
        int k = idx >> 11;
        int r0 = lane >> 2, cp = (lane & 3) * 2;
        for (int ai = 0; ai < 4; ai++) {
            int row = ot * 16 + r0 + (ai & 1) * 8;
            int col = ct * 16 + cp + (ai >> 1) * 8;
            float v0 = w2[(col * KCH + k + 1) * HID + row];
            float v1 = w2[((col + 1) * KCH + k + 1) * HID + row];
            g_W2fh[k][ot][ct][lane][ai] =
                pack_hh(__float2half_rn(v0), __float2half_rn(v1));
        }
    }
    // FC weights in epilogue fragment order
    for (int idx = tid; idx < 8192; idx += blockDim.x) {
        int e = idx & 3;
        int lane = (idx >> 2) & 31;
        int j = (idx >> 7) & 3;
        int t = (idx >> 9) & 1;
        int wb = (idx >> 10) & 3;
        int cls = idx >> 12;
        int o2 = wb * 32 + t * 16 + (lane >> 2) + ((e >> 1) << 3);
        int nn = j * 8 + ((lane & 3) << 1) + (e & 1);
        g_FCf[cls][wb][t][j][lane][e] = fc_w[cls * 4096 + nn * HID + o2];
    }
    if (tid < HID) {
        float s1 = b1[tid];
        for (int c = 0; c < CIN; c++) s1 += w1[(c * KCH) * HID + tid];
        g_B1[tid] = s1;
        float sb = b2[tid];
        for (int c = 0; c < HID; c++) sb += w2[(c * KCH) * HID + tid];
        g_B2[tid] = sb;
    }
}

// ------------------------------------------------------------------
__device__ __forceinline__ uint32_t smem_u32(const void* p) {
    uint32_t a;
    asm("{ .reg .u64 t; cvta.to.shared.u64 t, %1; cvt.u32.u64 %0, t; }"
        : "=r"(a) : "l"(p));
    return a;
}
__device__ __forceinline__ void ldsm4(uint32_t* r, uint32_t addr) {
    asm volatile("ldmatrix.sync.aligned.m8n8.x4.shared.b16 {%0,%1,%2,%3}, [%4];\n"
                 : "=r"(r[0]), "=r"(r[1]), "=r"(r[2]), "=r"(r[3]) : "r"(addr));
}
__device__ __forceinline__ void mma16816(float* d, const uint32_t* a,
                                         uint32_t b0, uint32_t b1) {
    asm volatile(
        "mma.sync.aligned.m16n8k16.row.col.f32.f16.f16.f32 "
        "{%0,%1,%2,%3},{%4,%5,%6,%7},{%8,%9},{%0,%1,%2,%3};\n"
        : "+f"(d[0]), "+f"(d[1]), "+f"(d[2]), "+f"(d[3])
        : "r"(a[0]), "r"(a[1]), "r"(a[2]), "r"(a[3]), "r"(b0), "r"(b1));
}
__device__ __forceinline__ uint32_t pack2(float x, float y) {
    __half2 h = __float22half2_rn(make_float2(x, y));
    return *(uint32_t*)&h;
}

// ---- smem strides (halfs) ----
#define STX 72    // layer1 X rows: [hi 0..63 | pad]
#define STH 136   // layer2 H rows: [hi 0..127 | pad]

// ---- smem regions (bytes), per CTA (1 batch) ----
#define OFF_R1  0        // [32][STH]  X (l1, stride STX) / H (l2, stride STH) 8704
#define OFF_B1  8704
#define OFF_B2  9216
#define OFF_RED 9728     // 4 warps * 2 floats
#define SMEM_TOTAL 9856

// A-apply, register-chained, 1-pass: acc += Zh x Ah (Ah direct from gmem frags)
__device__ __forceinline__ void apply_chain(float (&acc)[2][4][4],
                                            const float (&d)[2][4][4],
                                            int k, int lane) {
    uint32_t zh2[2][4][2];
#pragma unroll
    for (int t = 0; t < 2; t++)
#pragma unroll
        for (int j = 0; j < 4; j++)
#pragma unroll
            for (int pr = 0; pr < 2; pr++)
                zh2[t][j][pr] = pack2(d[t][j][pr * 2 + 0], d[t][j][pr * 2 + 1]);
#pragma unroll
    for (int kh = 0; kh < 2; kh++) {
        uint4 b0 = *(const uint4*)g_Af[k][kh][0][lane];
        uint4 b1 = *(const uint4*)g_Af[k][kh][1][lane];
#pragma unroll
        for (int t = 0; t < 2; t++) {
            uint32_t Ah_[4] = {zh2[t][2 * kh][0], zh2[t][2 * kh][1],
                               zh2[t][2 * kh + 1][0], zh2[t][2 * kh + 1][1]};
            mma16816(acc[t][0], Ah_, b0.x, b0.z);
            mma16816(acc[t][1], Ah_, b0.y, b0.w);
            mma16816(acc[t][2], Ah_, b1.x, b1.z);
            mma16816(acc[t][3], Ah_, b1.y, b1.w);
        }
    }
}

// ------------------------------------------------------------------
__global__ __launch_bounds__(128, 4) void dgcnn_mma_kernel(
    const float* __restrict__ x,
    const float* __restrict__ fcb,
    float* __restrict__ out) {

    extern __shared__ char smem[];
    __half* S = (__half*)smem;
    const uint32_t sb = smem_u32(smem);
    const int tid = threadIdx.x;
    const int wb = tid >> 5, lane = tid & 31;   // o-quarter

    float* sB1 = (float*)(smem + OFF_B1);
    float* sB2 = (float*)(smem + OFF_B2);
    float* red = (float*)(smem + OFF_RED);

    // ---- prologue: X hi staging with inline zero-pad ----
    {
        const float* xb = x + (size_t)blockIdx.x * 32 * CIN;
        for (int i = tid; i < 32 * 16; i += 128) {
            int row = i >> 4, g = i & 15;
            uint2 hi;
            if (g == 15) {
                hi.x = 0u; hi.y = 0u;
            } else {
                float4 v = *(const float4*)&xb[row * CIN + g * 4];
                hi.x = pack_hh(__float2half_rn(v.x), __float2half_rn(v.y));
                hi.y = pack_hh(__float2half_rn(v.z), __float2half_rn(v.w));
            }
            *(uint2*)&S[row * STX + g * 4] = hi;
        }
        if (tid < 128) { sB1[tid] = g_B1[tid]; sB2[tid] = g_B2[tid]; }
    }
    __syncthreads();

    const uint32_t bX = sb + OFF_R1;
    const uint32_t bH = sb + OFF_R1;
    const uint32_t lrow = (uint32_t)(lane & 15);
    const uint32_t lcol = (uint32_t)((lane >> 4) << 3);

    float acc[2][4][4];
#pragma unroll
    for (int t = 0; t < 2; t++)
#pragma unroll
        for (int j = 0; j < 4; j++)
#pragma unroll
            for (int e = 0; e < 4; e++) acc[t][j][e] = 0.0f;

    // ================= layer 1 (hi-only) =================
    for (int k = 0; k < 4; k++) {
        float d[2][4][4];
#pragma unroll
        for (int t = 0; t < 2; t++)
#pragma unroll
            for (int j = 0; j < 4; j++)
#pragma unroll
                for (int e = 0; e < 4; e++) d[t][j][e] = 0.0f;

#pragma unroll
        for (int c = 0; c < 4; c++) {
            uint4 ah0 = *(const uint4*)g_W1fh[k][wb * 2 + 0][c][lane];
            uint4 ah1 = *(const uint4*)g_W1fh[k][wb * 2 + 1][c][lane];
            uint32_t Ah0[4] = {ah0.x, ah0.y, ah0.z, ah0.w};
            uint32_t Ah1[4] = {ah1.x, ah1.y, ah1.z, ah1.w};
            uint32_t Bh[2][4];
#pragma unroll
            for (int np = 0; np < 2; np++)
                ldsm4(Bh[np], bX + ((np * 16 + lrow) * STX + c * 16 + lcol) * 2);
#pragma unroll
            for (int np = 0; np < 2; np++) {
                mma16816(d[0][np * 2 + 0], Ah0, Bh[np][0], Bh[np][2]);
                mma16816(d[0][np * 2 + 1], Ah0, Bh[np][1], Bh[np][3]);
                mma16816(d[1][np * 2 + 0], Ah1, Bh[np][0], Bh[np][2]);
                mma16816(d[1][np * 2 + 1], Ah1, Bh[np][1], Bh[np][3]);
            }
        }
        if (k == 0) {
#pragma unroll
            for (int t = 0; t < 2; t++)
#pragma unroll
                for (int j = 0; j < 4; j++)
#pragma unroll
                    for (int e = 0; e < 4; e++) acc[t][j][e] += d[t][j][e];
        } else {
            apply_chain(acc, d, k, lane);
        }
    }

    // H1 = relu(acc + b1) -> R1 [row][o], stride STH
    __syncthreads();
#pragma unroll
    for (int t = 0; t < 2; t++)
#pragma unroll
        for (int j = 0; j < 4; j++)
#pragma unroll
            for (int e = 0; e < 4; e++) {
                int o = wb * 32 + t * 16 + (lane >> 2) + ((e >> 1) << 3);
                int n = j * 8 + ((lane & 3) << 1) + (e & 1);
                float v = fmaxf(acc[t][j][e] + sB1[o], 0.0f);
                S[n * STH + o] = __float2half_rn(v);
            }
#pragma unroll
    for (int t = 0; t < 2; t++)
#pragma unroll
        for (int j = 0; j < 4; j++)
#pragma unroll
            for (int e = 0; e < 4; e++) acc[t][j][e] = 0.0f;
    __syncthreads();

    // ================= layer 2 (hi-only) =================
    for (int k2 = 0; k2 < 4; k2++) {
        float d[2][4][4];
#pragma unroll
        for (int t = 0; t < 2; t++)
#pragma unroll
            for (int j = 0; j < 4; j++)
#pragma unroll
                for (int e = 0; e < 4; e++) d[t][j][e] = 0.0f;

#pragma unroll
        for (int c = 0; c < 8; c++) {
            uint4 ah0 = *(const uint4*)g_W2fh[k2][wb * 2 + 0][c][lane];
            uint4 ah1 = *(const uint4*)g_W2fh[k2][wb * 2 + 1][c][lane];
            uint32_t Ah0[4] = {ah0.x, ah0.y, ah0.z, ah0.w};
            uint32_t Ah1[4] = {ah1.x, ah1.y, ah1.z, ah1.w};
#pragma unroll
            for (int np = 0; np < 2; np++) {
                uint32_t Bf[4];
                ldsm4(Bf, bH + ((np * 16 + lrow) * STH + c * 16 + lcol) * 2);
                mma16816(d[0][np * 2 + 0], Ah0, Bf[0], Bf[2]);
                mma16816(d[0][np * 2 + 1], Ah0, Bf[1], Bf[3]);
                mma16816(d[1][np * 2 + 0], Ah1, Bf[0], Bf[2]);
                mma16816(d[1][np * 2 + 1], Ah1, Bf[1], Bf[3]);
            }
        }
        if (k2 == 0) {
#pragma unroll
            for (int t = 0; t < 2; t++)
#pragma unroll
                for (int j = 0; j < 4; j++)
#pragma unroll
                    for (int e = 0; e < 4; e++) acc[t][j][e] += d[t][j][e];
        } else {
            apply_chain(acc, d, k2, lane);
        }
    }

    // ---- FC epilogue (coalesced fragment LDG, no smem) ----
    float p0 = 0.0f, p1 = 0.0f;
#pragma unroll
    for (int t = 0; t < 2; t++)
#pragma unroll
        for (int j = 0; j < 4; j++) {
            float4 f0 = *(const float4*)g_FCf[0][wb][t][j][lane];
            float4 f1 = *(const float4*)g_FCf[1][wb][t][j][lane];
            float v0, v1, v2, v3;
            {
                int ob = wb * 32 + t * 16 + (lane >> 2);
                v0 = fmaxf(acc[t][j][0] + sB2[ob], 0.0f);
                v1 = fmaxf(acc[t][j][1] + sB2[ob], 0.0f);
                v2 = fmaxf(acc[t][j][2] + sB2[ob + 8], 0.0f);
                v3 = fmaxf(acc[t][j][3] + sB2[ob + 8], 0.0f);
            }
            p0 += v0 * f0.x + v1 * f0.y + v2 * f0.z + v3 * f0.w;
            p1 += v0 * f1.x + v1 * f1.y + v2 * f1.z + v3 * f1.w;
        }
#pragma unroll
    for (int off = 16; off > 0; off >>= 1) {
        p0 += __shfl_xor_sync(0xFFFFFFFFu, p0, off);
        p1 += __shfl_xor_sync(0xFFFFFFFFu, p1, off);
    }
    if (lane == 0) { red[wb * 2] = p0; red[wb * 2 + 1] = p1; }
    __syncthreads();
    if (tid < 2) {
        float s = red[0 * 2 + tid] + red[1 * 2 + tid] +
                  red[2 * 2 + tid] + red[3 * 2 + tid];
        out[blockIdx.x * 2 + tid] = s + fcb[tid];
    }
}

// ------------------------------------------------------------------
extern "C" void kernel_launch(void* const* d_in, const int* in_sizes, int n_in,
                              void* d_out, int out_size) {
    const float* x        = (const float*)d_in[0];
    const float* adj      = (const float*)d_in[1];
    const float* adj_bias = (const float*)d_in[2];
    const float* w1       = (const float*)d_in[3];
    const float* b1       = (const float*)d_in[4];
    const float* w2       = (const float*)d_in[5];
    const float* b2       = (const float*)d_in[6];
    const float* fc_w     = (const float*)d_in[7];
    const float* fc_b     = (const float*)d_in[8];
    float* out = (float*)d_out;

    const int B = in_sizes[0] / (NNODE * CIN);

    cudaFuncSetAttribute(dgcnn_mma_kernel,
                         cudaFuncAttributeMaxDynamicSharedMemorySize,
                         SMEM_TOTAL);

    precompute_kernel<<<1, 1024>>>(adj, adj_bias, w1, b1, w2, b2, fc_w);
    dgcnn_mma_kernel<<<B, 128, SMEM_TOTAL>>>(x, fc_b, out);
}

// round 15
// speedup vs baseline: 1.4086x; 1.4086x over previous
#include <cuda_runtime.h>
#include <cuda_fp16.h>
#include <cstdint>

#define NNODE 32
#define CIN   60
#define HID   128
#define KCH   5

// ---- fragment-order packed constants (all L2-resident, loaded direct) ----
__device__ __align__(16) uint32_t g_W1fh[4][8][4][32][4];  // A-op frag, layer1
__device__ __align__(16) uint32_t g_W2fh[4][8][8][32][4];  // A-op frag, layer2
__device__ __align__(16) uint32_t g_Af[4][2][2][32][4];    // B-op frag, chebyshev
__device__ __align__(16) float    g_FCf[2][4][2][4][32][4];// FC frag order
__device__ float g_B1[128];
__device__ float g_B2[128];

__device__ __forceinline__ uint32_t pack_hh(__half a, __half b) {
    return (uint32_t)__half_as_ushort(a) | ((uint32_t)__half_as_ushort(b) << 16);
}

// ------------------------------------------------------------------
__global__ void precompute_kernel(const float* __restrict__ adj,
                                  const float* __restrict__ adj_bias,
                                  const float* __restrict__ w1,
                                  const float* __restrict__ b1,
                                  const float* __restrict__ w2,
                                  const float* __restrict__ b2,
                                  const float* __restrict__ fc_w) {
    __shared__ float a[NNODE][NNODE];
    __shared__ float L[NNODE][NNODE];
    __shared__ float A3[NNODE][NNODE];
    __shared__ float A4[NNODE][NNODE];
    __shared__ float dre[NNODE];

    int tid = threadIdx.x;
    int n = tid >> 5, m = tid & 31;

    float bias = adj_bias[0];
    a[n][m] = fmaxf(adj[n * NNODE + m] + bias, 0.0f);
    __syncthreads();
    if (m == 0) {
        float s = 0.0f;
        for (int j = 0; j < NNODE; j++) s += a[n][j];
        dre[n] = 1.0f / sqrtf(s + 1e-5f);
    }
    __syncthreads();
    L[n][m] = (n == m ? 1.0f : 0.0f) - dre[n] * a[n][m] * dre[m];
    __syncthreads();
    float s = 0.0f;
    for (int j = 0; j < NNODE; j++) s += L[n][j] * L[j][m];
    A3[n][m] = 2.0f * s - (n == m ? 1.0f : 0.0f);
    __syncthreads();
    float s2 = 0.0f;
    for (int j = 0; j < NNODE; j++) s2 += L[n][j] * A3[j][m];
    A4[n][m] = 2.0f * s2 - L[n][m];
    __syncthreads();

    // Chebyshev B-operand fragments (ldsm.m8n8.x4 emulation)
    for (int idx = tid; idx < 4 * 2 * 2 * 32; idx += blockDim.x) {
        int lane = idx & 31;
        int np = (idx >> 5) & 1;
        int kh = (idx >> 6) & 1;
        int k = idx >> 7;
        for (int q = 0; q < 4; q++) {
            int rn = np * 16 + (q & 1) * 8 + (lane >> 2);
            int cm = kh * 16 + (q >> 1) * 8 + 2 * (lane & 3);
            float v0, v1;
            if (k == 0)      { v0 = (rn == cm) ? 1.0f : 0.0f; v1 = (rn == cm + 1) ? 1.0f : 0.0f; }
            else if (k == 1) { v0 = L[rn][cm];  v1 = L[rn][cm + 1]; }
            else if (k == 2) { v0 = A3[rn][cm]; v1 = A3[rn][cm + 1]; }
            else             { v0 = A4[rn][cm]; v1 = A4[rn][cm + 1]; }
            g_Af[k][kh][np][lane][q] =
                pack_hh(__float2half_rn(v0), __float2half_rn(v1));
        }
    }

    // W1 fragments: row=o, col=c (zero pad c>=60)
    for (int idx = tid; idx < 4 * 8 * 4 * 32; idx += blockDim.x) {
        int lane = idx & 31;
        int ct = (idx >> 5) & 3;
        int ot = (idx >> 7) & 7;
        int k = idx >> 10;
        int r0 = lane >> 2, cp = (lane & 3) * 2;
        for (int ai = 0; ai < 4; ai++) {
            int row = ot * 16 + r0 + (ai & 1) * 8;
            int col = ct * 16 + cp + (ai >> 1) * 8;
            float v0 = (col < CIN) ? w1[(col * KCH + k + 1) * HID + row] : 0.0f;
            float v1 = (col + 1 < CIN) ? w1[((col + 1) * KCH + k + 1) * HID + row] : 0.0f;
            g_W1fh[k][ot][ct][lane][ai] =
                pack_hh(__float2half_rn(v0), __float2half_rn(v1));
        }
    }
    // W2 fragments: row=o2, col=o
    for (int idx = tid; idx < 4 * 8 * 8 * 32; idx += blockDim.x) {
        int lane = idx & 31;
        int ct = (idx >> 5) & 7;
        int ot = (idx >> 8) & 7;
        int k = idx >> 11;
        int r0 = lane >> 2, cp = (lane & 3) * 2;
        for (int ai = 0; ai < 4; ai++) {
            int row = ot * 16 + r0 + (ai & 1) * 8;
            int col = ct * 16 + cp + (ai >> 1) * 8;
            float v0 = w2[(col * KCH + k + 1) * HID + row];
            float v1 = w2[((col + 1) * KCH + k + 1) * HID + row];
            g_W2fh[k][ot][ct][lane][ai] =
                pack_hh(__float2half_rn(v0), __float2half_rn(v1));
        }
    }
    // FC weights in epilogue fragment order
    for (int idx = tid; idx < 8192; idx += blockDim.x) {
        int e = idx & 3;
        int lane = (idx >> 2) & 31;
        int j = (idx >> 7) & 3;
        int t = (idx >> 9) & 1;
        int wb = (idx >> 10) & 3;
        int cls = idx >> 12;
        int o2 = wb * 32 + t * 16 + (lane >> 2) + ((e >> 1) << 3);
        int nn = j * 8 + ((lane & 3) << 1) + (e & 1);
        g_FCf[cls][wb][t][j][lane][e] = fc_w[cls * 4096 + nn * HID + o2];
    }
    if (tid < HID) {
        float s1 = b1[tid];
        for (int c = 0; c < CIN; c++) s1 += w1[(c * KCH) * HID + tid];
        g_B1[tid] = s1;
        float sb = b2[tid];
        for (int c = 0; c < HID; c++) sb += w2[(c * KCH) * HID + tid];
        g_B2[tid] = sb;
    }
}

// ------------------------------------------------------------------
__device__ __forceinline__ uint32_t smem_u32(const void* p) {
    uint32_t a;
    asm("{ .reg .u64 t; cvta.to.shared.u64 t, %1; cvt.u32.u64 %0, t; }"
        : "=r"(a) : "l"(p));
    return a;
}
__device__ __forceinline__ void ldsm4(uint32_t* r, uint32_t addr) {
    asm volatile("ldmatrix.sync.aligned.m8n8.x4.shared.b16 {%0,%1,%2,%3}, [%4];\n"
                 : "=r"(r[0]), "=r"(r[1]), "=r"(r[2]), "=r"(r[3]) : "r"(addr));
}
__device__ __forceinline__ void mma16816(float* d, const uint32_t* a,
                                         uint32_t b0, uint32_t b1) {
    asm volatile(
        "mma.sync.aligned.m16n8k16.row.col.f32.f16.f16.f32 "
        "{%0,%1,%2,%3},{%4,%5,%6,%7},{%8,%9},{%0,%1,%2,%3};\n"
        : "+f"(d[0]), "+f"(d[1]), "+f"(d[2]), "+f"(d[3])
        : "r"(a[0]), "r"(a[1]), "r"(a[2]), "r"(a[3]), "r"(b0), "r"(b1));
}
__device__ __forceinline__ uint32_t pack2(float x, float y) {
    __half2 h = __float22half2_rn(make_float2(x, y));
    return *(uint32_t*)&h;
}

// ---- smem strides (halfs) ----
#define STX 72    // layer1 X rows: [hi 0..63 | pad]
#define STH 136   // layer2 H rows: [hi 0..127 | pad]

// ---- smem regions (bytes) ----
#define OFF_R1  0        // [64][STH]  X (l1, stride STX) / H (l2, stride STH)
#define OFF_B1  17408
#define OFF_B2  17920
#define OFF_RED 18432
#define SMEM_TOTAL 18560

// A-apply, register-chained, 1-pass: acc += Zh x Ah (Ah direct from gmem frags)
__device__ __forceinline__ void apply_chain(float (&acc)[2][4][4],
                                            const float (&d)[2][4][4],
                                            int k, int lane) {
    uint32_t zh2[2][4][2];
#pragma unroll
    for (int t = 0; t < 2; t++)
#pragma unroll
        for (int j = 0; j < 4; j++)
#pragma unroll
            for (int pr = 0; pr < 2; pr++)
                zh2[t][j][pr] = pack2(d[t][j][pr * 2 + 0], d[t][j][pr * 2 + 1]);
#pragma unroll
    for (int kh = 0; kh < 2; kh++) {
        uint4 b0 = __ldg((const uint4*)g_Af[k][kh][0][lane]);
        uint4 b1 = __ldg((const uint4*)g_Af[k][kh][1][lane]);
#pragma unroll
        for (int t = 0; t < 2; t++) {
            uint32_t Ah_[4] = {zh2[t][2 * kh][0], zh2[t][2 * kh][1],
                               zh2[t][2 * kh + 1][0], zh2[t][2 * kh + 1][1]};
            mma16816(acc[t][0], Ah_, b0.x, b0.z);
            mma16816(acc[t][1], Ah_, b0.y, b0.w);
            mma16816(acc[t][2], Ah_, b1.x, b1.z);
            mma16816(acc[t][3], Ah_, b1.y, b1.w);
        }
    }
}

// ------------------------------------------------------------------
__global__ __launch_bounds__(256, 2) void dgcnn_mma_kernel(
    const float* __restrict__ x,
    const float* __restrict__ fcb,
    float* __restrict__ out) {

    extern __shared__ char smem[];
    __half* S = (__half*)smem;
    const uint32_t sb = smem_u32(smem);
    const int tid = threadIdx.x;
    const int w = tid >> 5, lane = tid & 31;
    const int bp = w >> 2, wb = w & 3;       // batch (0..1), o-quarter

    float* sB1 = (float*)(smem + OFF_B1);
    float* sB2 = (float*)(smem + OFF_B2);
    float* red = (float*)(smem + OFF_RED);

    // ---- prologue: X hi staging with inline zero-pad (no pre-zero pass) ----
    {
        const float* xb = x + (size_t)blockIdx.x * 64 * CIN;
        for (int i = tid; i < 64 * 16; i += 256) {
            int row = i >> 4, g = i & 15;
            uint2 hi;
            if (g == 15) {
                hi.x = 0u; hi.y = 0u;
            } else {
                float4 v = *(const float4*)&xb[row * CIN + g * 4];
                hi.x = pack_hh(__float2half_rn(v.x), __float2half_rn(v.y));
                hi.y = pack_hh(__float2half_rn(v.z), __float2half_rn(v.w));
            }
            *(uint2*)&S[row * STX + g * 4] = hi;
        }
        if (tid < 128) { sB1[tid] = g_B1[tid]; sB2[tid] = g_B2[tid]; }
    }
    __syncthreads();

    const uint32_t bX = sb + OFF_R1 + (bp * 32) * STX * 2;
    const uint32_t bH = sb + OFF_R1 + (bp * 32) * STH * 2;
    const uint32_t lrow = (uint32_t)(lane & 15);
    const uint32_t lcol = (uint32_t)((lane >> 4) << 3);

    float acc[2][4][4];
#pragma unroll
    for (int t = 0; t < 2; t++)
#pragma unroll
        for (int j = 0; j < 4; j++)
#pragma unroll
            for (int e = 0; e < 4; e++) acc[t][j][e] = 0.0f;

    // ================= layer 1 (hi-only, rolled k) =================
    for (int k = 0; k < 4; k++) {
        float d[2][4][4];
#pragma unroll
        for (int t = 0; t < 2; t++)
#pragma unroll
            for (int j = 0; j < 4; j++)
#pragma unroll
                for (int e = 0; e < 4; e++) d[t][j][e] = 0.0f;

#pragma unroll
        for (int c = 0; c < 4; c++) {
            uint4 ah0 = __ldg((const uint4*)g_W1fh[k][wb * 2 + 0][c][lane]);
            uint4 ah1 = __ldg((const uint4*)g_W1fh[k][wb * 2 + 1][c][lane]);
            uint32_t Ah0[4] = {ah0.x, ah0.y, ah0.z, ah0.w};
            uint32_t Ah1[4] = {ah1.x, ah1.y, ah1.z, ah1.w};
            uint32_t Bh[2][4];
#pragma unroll
            for (int np = 0; np < 2; np++)
                ldsm4(Bh[np], bX + ((np * 16 + lrow) * STX + c * 16 + lcol) * 2);
#pragma unroll
            for (int np = 0; np < 2; np++) {
                mma16816(d[0][np * 2 + 0], Ah0, Bh[np][0], Bh[np][2]);
                mma16816(d[0][np * 2 + 1], Ah0, Bh[np][1], Bh[np][3]);
                mma16816(d[1][np * 2 + 0], Ah1, Bh[np][0], Bh[np][2]);
                mma16816(d[1][np * 2 + 1], Ah1, Bh[np][1], Bh[np][3]);
            }
        }
        if (k == 0) {
#pragma unroll
            for (int t = 0; t < 2; t++)
#pragma unroll
                for (int j = 0; j < 4; j++)
#pragma unroll
                    for (int e = 0; e < 4; e++) acc[t][j][e] += d[t][j][e];
        } else {
            apply_chain(acc, d, k, lane);
        }
    }

    // H1 = relu(acc + b1) -> R1 [row][o], stride STH
    __syncthreads();
#pragma unroll
    for (int t = 0; t < 2; t++)
#pragma unroll
        for (int j = 0; j < 4; j++)
#pragma unroll
            for (int e = 0; e < 4; e++) {
                int o = wb * 32 + t * 16 + (lane >> 2) + ((e >> 1) << 3);
                int n = j * 8 + ((lane & 3) << 1) + (e & 1);
                float v = fmaxf(acc[t][j][e] + sB1[o], 0.0f);
                S[(bp * 32 + n) * STH + o] = __float2half_rn(v);
            }
#pragma unroll
    for (int t = 0; t < 2; t++)
#pragma unroll
        for (int j = 0; j < 4; j++)
#pragma unroll
            for (int e = 0; e < 4; e++) acc[t][j][e] = 0.0f;
    __syncthreads();

    // ================= layer 2 (hi-only, rolled k2) =================
    for (int k2 = 0; k2 < 4; k2++) {
        float d[2][4][4];
#pragma unroll
        for (int t = 0; t < 2; t++)
#pragma unroll
            for (int j = 0; j < 4; j++)
#pragma unroll
                for (int e = 0; e < 4; e++) d[t][j][e] = 0.0f;

#pragma unroll
        for (int c = 0; c < 8; c++) {
            uint4 ah0 = __ldg((const uint4*)g_W2fh[k2][wb * 2 + 0][c][lane]);
            uint4 ah1 = __ldg((const uint4*)g_W2fh[k2][wb * 2 + 1][c][lane]);
            uint32_t Ah0[4] = {ah0.x, ah0.y, ah0.z, ah0.w};
            uint32_t Ah1[4] = {ah1.x, ah1.y, ah1.z, ah1.w};
#pragma unroll
            for (int np = 0; np < 2; np++) {
                uint32_t Bf[4];
                ldsm4(Bf, bH + ((np * 16 + lrow) * STH + c * 16 + lcol) * 2);
                mma16816(d[0][np * 2 + 0], Ah0, Bf[0], Bf[2]);
                mma16816(d[0][np * 2 + 1], Ah0, Bf[1], Bf[3]);
                mma16816(d[1][np * 2 + 0], Ah1, Bf[0], Bf[2]);
                mma16816(d[1][np * 2 + 1], Ah1, Bf[1], Bf[3]);
            }
        }
        if (k2 == 0) {
#pragma unroll
            for (int t = 0; t < 2; t++)
#pragma unroll
                for (int j = 0; j < 4; j++)
#pragma unroll
                    for (int e = 0; e < 4; e++) acc[t][j][e] += d[t][j][e];
        } else {
            apply_chain(acc, d, k2, lane);
        }
    }

    // ---- FC epilogue (coalesced fragment LDG, no smem) ----
    float p0 = 0.0f, p1 = 0.0f;
#pragma unroll
    for (int t = 0; t < 2; t++)
#pragma unroll
        for (int j = 0; j < 4; j++) {
            float4 f0 = __ldg((const float4*)g_FCf[0][wb][t][j][lane]);
            float4 f1 = __ldg((const float4*)g_FCf[1][wb][t][j][lane]);
            float v0, v1, v2, v3;
            {
                int ob = wb * 32 + t * 16 + (lane >> 2);
                v0 = fmaxf(acc[t][j][0] + sB2[ob], 0.0f);
                v1 = fmaxf(acc[t][j][1] + sB2[ob], 0.0f);
                v2 = fmaxf(acc[t][j][2] + sB2[ob + 8], 0.0f);
                v3 = fmaxf(acc[t][j][3] + sB2[ob + 8], 0.0f);
            }
            p0 += v0 * f0.x + v1 * f0.y + v2 * f0.z + v3 * f0.w;
            p1 += v0 * f1.x + v1 * f1.y + v2 * f1.z + v3 * f1.w;
        }
#pragma unroll
    for (int off = 16; off > 0; off >>= 1) {
        p0 += __shfl_xor_sync(0xFFFFFFFFu, p0, off);
        p1 += __shfl_xor_sync(0xFFFFFFFFu, p1, off);
    }
    if (lane == 0) { red[w * 2] = p0; red[w * 2 + 1] = p1; }
    __syncthreads();
    if (tid < 4) {
        int b2 = tid >> 1, c = tid & 1;
        float s = red[(b2 * 4 + 0) * 2 + c] + red[(b2 * 4 + 1) * 2 + c] +
                  red[(b2 * 4 + 2) * 2 + c] + red[(b2 * 4 + 3) * 2 + c];
        out[(blockIdx.x * 2 + b2) * 2 + c] = s + fcb[c];
    }
}

// ------------------------------------------------------------------
extern "C" void kernel_launch(void* const* d_in, const int* in_sizes, int n_in,
                              void* d_out, int out_size) {
    const float* x        = (const float*)d_in[0];
    const float* adj      = (const float*)d_in[1];
    const float* adj_bias = (const float*)d_in[2];
    const float* w1       = (const float*)d_in[3];
    const float* b1       = (const float*)d_in[4];
    const float* w2       = (const float*)d_in[5];
    const float* b2       = (const float*)d_in[6];
    const float* fc_w     = (const float*)d_in[7];
    const float* fc_b     = (const float*)d_in[8];
    float* out = (float*)d_out;

    const int B = in_sizes[0] / (NNODE * CIN);

    cudaFuncSetAttribute(dgcnn_mma_kernel,
                         cudaFuncAttributeMaxDynamicSharedMemorySize,
                         SMEM_TOTAL);

    precompute_kernel<<<1, 1024>>>(adj, adj_bias, w1, b1, w2, b2, fc_w);
    dgcnn_mma_kernel<<<B / 2, 256, SMEM_TOTAL>>>(x, fc_b, out);
}